// round 3
// baseline (speedup 1.0000x reference)
#include <cuda_runtime.h>
#include <cstdint>

#define SEQ   1024
#define HID   2048
#define K2DIM 4096
#define VOC   129280
#define EPSV  1e-6f

// ---------------- scratch (device globals, no allocation) ----------------
__device__ float g_combined[SEQ * K2DIM];   // 16 MB
__device__ float g_proj[SEQ * HID];         // 8 MB
__device__ float g_normed[SEQ * HID];       // 8 MB
__device__ float g_nll[SEQ];

// ---------------- helpers ----------------
__device__ __forceinline__ bool detect_i64(const int* w) {
    // If buffer is int64 (values < 2^31), odd 32-bit words of the first 16
    // entries are all zero. For int32 data the chance of 16 zeros is ~0.
    bool z = true;
#pragma unroll
    for (int j = 1; j < 32; j += 2) z = z && (w[j] == 0);
    return z;
}
__device__ __forceinline__ int load_idx(const void* p, int i, bool is64) {
    return is64 ? (int)((const long long*)p)[i] : ((const int*)p)[i];
}

__device__ __forceinline__ float block_sum256(float v, volatile float* red) {
#pragma unroll
    for (int o = 16; o > 0; o >>= 1) v += __shfl_xor_sync(0xffffffffu, v, o);
    if ((threadIdx.x & 31) == 0) red[threadIdx.x >> 5] = v;
    __syncthreads();
    float t = red[0] + red[1] + red[2] + red[3] + red[4] + red[5] + red[6] + red[7];
    __syncthreads();
    return t;
}

// ---------------- kernel A: gather + enorm + hnorm + concat ----------------
__global__ void __launch_bounds__(256) prep_kernel(
    const float* __restrict__ hidden, const void* __restrict__ ids,
    const float* __restrict__ embed_w, const float* __restrict__ enorm_w,
    const float* __restrict__ hnorm_w, float* __restrict__ combined)
{
    __shared__ float s_e[HID];
    __shared__ float s_h[HID];
    __shared__ float red[8];
    __shared__ int s_id;
    int tid = threadIdx.x, sid = blockIdx.x;
    if (tid == 0) {
        bool is64 = detect_i64((const int*)ids);
        s_id = load_idx(ids, sid, is64);
    }
    __syncthreads();
    const float* erow = embed_w + (size_t)s_id * HID;
    const float* hrow = hidden + (size_t)sid * HID;
    float se = 0.f, sh = 0.f;
    for (int j = tid; j < HID; j += 256) {
        float e = erow[j], h = hrow[j];
        s_e[j] = e; s_h[j] = h;
        se += e * e; sh += h * h;
    }
    float vse = block_sum256(se, red);
    float vsh = block_sum256(sh, red);
    float re = rsqrtf(vse / HID + EPSV);
    float rh = rsqrtf(vsh / HID + EPSV);
    float* out = combined + (size_t)sid * K2DIM;
    for (int j = tid; j < HID; j += 256) {
        out[j]       = enorm_w[j] * s_e[j] * re;
        out[HID + j] = hnorm_w[j] * s_h[j] * rh;
    }
}

// ---------------- kernel C: double RMSNorm (ln then norm) ----------------
__global__ void __launch_bounds__(256) norm2_kernel(
    const float* __restrict__ x, const float* __restrict__ lnw,
    const float* __restrict__ nw, float* __restrict__ out)
{
    __shared__ float sx[HID];
    __shared__ float red[8];
    int sid = blockIdx.x, tid = threadIdx.x;
    const float* row = x + (size_t)sid * HID;
    float ss = 0.f;
    for (int j = tid; j < HID; j += 256) { float v = row[j]; sx[j] = v; ss += v * v; }
    float r1 = rsqrtf(block_sum256(ss, red) / HID + EPSV);
    float ss2 = 0.f;
    for (int j = tid; j < HID; j += 256) { float p = lnw[j] * sx[j] * r1; sx[j] = p; ss2 += p * p; }
    float r2 = rsqrtf(block_sum256(ss2, red) / HID + EPSV);
    float* o = out + (size_t)sid * HID;
    for (int j = tid; j < HID; j += 256) o[j] = nw[j] * sx[j] * r2;
}

// ---------------- TF32 mma GEMM: C[M,N] = A[M,K] * B[N,K]^T ----------------
#define BM 128
#define BN 128
#define BK 32
#define LDT 36          // padded smem leading dim (LDT % 32 == 4 -> conflict-free frags)
#define SMEM_BYTES (4 * BM * LDT * 4)   // 2 stages * (A + B) tiles

__device__ __forceinline__ unsigned cvt_tf32(float x) {
    unsigned r; asm("cvt.rna.tf32.f32 %0, %1;" : "=r"(r) : "f"(x)); return r;
}
__device__ __forceinline__ void mma_tf32(float c[4], const unsigned a[4], const unsigned b[2]) {
    asm volatile(
        "mma.sync.aligned.m16n8k8.row.col.f32.tf32.tf32.f32 "
        "{%0,%1,%2,%3}, {%4,%5,%6,%7}, {%8,%9}, {%0,%1,%2,%3};"
        : "+f"(c[0]), "+f"(c[1]), "+f"(c[2]), "+f"(c[3])
        : "r"(a[0]), "r"(a[1]), "r"(a[2]), "r"(a[3]), "r"(b[0]), "r"(b[1]));
}
__device__ __forceinline__ void cp_async16(void* smem, const void* gmem) {
    unsigned sa = (unsigned)__cvta_generic_to_shared(smem);
    asm volatile("cp.async.ca.shared.global [%0], [%1], 16;" :: "r"(sa), "l"(gmem));
}
__device__ __forceinline__ void cp_commit() { asm volatile("cp.async.commit_group;"); }
__device__ __forceinline__ void cp_wait0() { asm volatile("cp.async.wait_group 0;"); }

__device__ __forceinline__ void load_tile(
    const float* __restrict__ Ab, const float* __restrict__ Bb,
    float* As, float* Bs, int K, int kt, int st, int tid)
{
    int k0 = kt * BK;
    float* as = As + st * (BM * LDT);
    float* bs = Bs + st * (BM * LDT);
#pragma unroll
    for (int i = 0; i < 4; i++) {
        int idx = tid + i * 256;
        int r = idx >> 3;
        int cg = (idx & 7) * 4;
        cp_async16(as + r * LDT + cg, Ab + (size_t)r * K + k0 + cg);
        cp_async16(bs + r * LDT + cg, Bb + (size_t)r * K + k0 + cg);
    }
}

template <bool SPLIT>
__global__ void __launch_bounds__(256) gemm_tf32_kernel(
    const float* __restrict__ A, const float* __restrict__ Bw,
    float* __restrict__ C, int M, int N, int K)
{
    extern __shared__ float smem[];
    float* As = smem;
    float* Bs = smem + 2 * BM * LDT;

    int tid = threadIdx.x;
    int lane = tid & 31;
    int warp = tid >> 5;
    int wm = warp & 1;   // 2 warps along M (64 rows each)
    int wn = warp >> 1;  // 4 warps along N (32 cols each)
    int bm = blockIdx.y * BM;
    int bn = blockIdx.x * BN;
    const float* Ab = A + (size_t)bm * K;
    const float* Bb = Bw + (size_t)bn * K;

    float acc[4][4][4];
#pragma unroll
    for (int i = 0; i < 4; i++)
#pragma unroll
        for (int j = 0; j < 4; j++)
#pragma unroll
            for (int q = 0; q < 4; q++) acc[i][j][q] = 0.f;

    int KT = K / BK;
    load_tile(Ab, Bb, As, Bs, K, 0, 0, tid);
    cp_commit();

    int gid = lane >> 2, tig = lane & 3;

    for (int kt = 0; kt < KT; ++kt) {
        int cur = kt & 1;
        cp_wait0();
        __syncthreads();
        if (kt + 1 < KT) { load_tile(Ab, Bb, As, Bs, K, kt + 1, cur ^ 1, tid); cp_commit(); }

        const float* Asc = As + cur * (BM * LDT);
        const float* Bsc = Bs + cur * (BM * LDT);
#pragma unroll
        for (int kk = 0; kk < BK; kk += 8) {
            unsigned af[4][4], bf[4][2];
            unsigned al[4][4], bl[4][2];
#pragma unroll
            for (int mi = 0; mi < 4; mi++) {
                const float* p = Asc + (wm * 64 + mi * 16 + gid) * LDT + kk + tig;
                float x0 = p[0], x1 = p[8 * LDT], x2 = p[4], x3 = p[8 * LDT + 4];
                af[mi][0] = cvt_tf32(x0); af[mi][1] = cvt_tf32(x1);
                af[mi][2] = cvt_tf32(x2); af[mi][3] = cvt_tf32(x3);
                if (SPLIT) {
                    al[mi][0] = cvt_tf32(x0 - __uint_as_float(af[mi][0]));
                    al[mi][1] = cvt_tf32(x1 - __uint_as_float(af[mi][1]));
                    al[mi][2] = cvt_tf32(x2 - __uint_as_float(af[mi][2]));
                    al[mi][3] = cvt_tf32(x3 - __uint_as_float(af[mi][3]));
                }
            }
#pragma unroll
            for (int ni = 0; ni < 4; ni++) {
                const float* p = Bsc + (wn * 32 + ni * 8 + gid) * LDT + kk + tig;
                float y0 = p[0], y1 = p[4];
                bf[ni][0] = cvt_tf32(y0); bf[ni][1] = cvt_tf32(y1);
                if (SPLIT) {
                    bl[ni][0] = cvt_tf32(y0 - __uint_as_float(bf[ni][0]));
                    bl[ni][1] = cvt_tf32(y1 - __uint_as_float(bf[ni][1]));
                }
            }
#pragma unroll
            for (int mi = 0; mi < 4; mi++)
#pragma unroll
                for (int ni = 0; ni < 4; ni++) {
                    mma_tf32(acc[mi][ni], af[mi], bf[ni]);
                    if (SPLIT) {
                        mma_tf32(acc[mi][ni], al[mi], bf[ni]);
                        mma_tf32(acc[mi][ni], af[mi], bl[ni]);
                    }
                }
        }
    }

    // epilogue
    float* Cb = C + (size_t)(bm + wm * 64) * N + bn + wn * 32;
#pragma unroll
    for (int mi = 0; mi < 4; mi++) {
#pragma unroll
        for (int ni = 0; ni < 4; ni++) {
            int r = mi * 16 + gid;
            int c = ni * 8 + tig * 2;
            float2 v0 = make_float2(acc[mi][ni][0], acc[mi][ni][1]);
            float2 v1 = make_float2(acc[mi][ni][2], acc[mi][ni][3]);
            *reinterpret_cast<float2*>(Cb + (size_t)r * N + c) = v0;
            *reinterpret_cast<float2*>(Cb + (size_t)(r + 8) * N + c) = v1;
        }
    }
}

// ---------------- loss: per-row online logsumexp ----------------
__global__ void __launch_bounds__(256) loss_kernel(
    const float* __restrict__ logits, const void* __restrict__ labels,
    const float* __restrict__ mask, float* __restrict__ nll_out)
{
    int s = blockIdx.x;      // 0 .. SEQ-2 (uses logits[s], labels[s+1])
    int tid = threadIdx.x;
    __shared__ int s_lab;
    if (tid == 0) {
        bool is64 = detect_i64((const int*)labels);
        s_lab = load_idx(labels, s + 1, is64);
    }
    __syncthreads();
    const float* row = logits + (size_t)s * VOC;

    float m = -1e30f, sum = 0.f;
    for (int j = tid; j < VOC; j += 256) {
        float x = row[j];
        if (x > m) { sum = sum * __expf(m - x) + 1.f; m = x; }
        else       { sum += __expf(x - m); }
    }
#pragma unroll
    for (int o = 16; o > 0; o >>= 1) {
        float om = __shfl_xor_sync(0xffffffffu, m, o);
        float os = __shfl_xor_sync(0xffffffffu, sum, o);
        float nm = fmaxf(m, om);
        sum = sum * __expf(m - nm) + os * __expf(om - nm);
        m = nm;
    }
    __shared__ float sm[8], ssu[8];
    if ((tid & 31) == 0) { sm[tid >> 5] = m; ssu[tid >> 5] = sum; }
    __syncthreads();
    if (tid == 0) {
        float M0 = sm[0], S0 = ssu[0];
#pragma unroll
        for (int i = 1; i < 8; i++) {
            float nm = fmaxf(M0, sm[i]);
            S0 = S0 * __expf(M0 - nm) + ssu[i] * __expf(sm[i] - nm);
            M0 = nm;
        }
        float lse = M0 + logf(S0);
        float nll = lse - row[s_lab];
        nll_out[s] = nll * mask[s + 1];
    }
}

__global__ void __launch_bounds__(256) final_kernel(
    const float* __restrict__ nll, const float* __restrict__ mask,
    float* __restrict__ out)
{
    __shared__ float red[8];
    int tid = threadIdx.x;
    float a = 0.f, b = 0.f;
    for (int j = tid; j < SEQ - 1; j += 256) { a += nll[j]; b += mask[j + 1]; }
    a = block_sum256(a, red);
    b = block_sum256(b, red);
    if (tid == 0) out[0] = a / (b + 1e-8f);
}

// ---------------- launch ----------------
extern "C" void kernel_launch(void* const* d_in, const int* in_sizes, int n_in,
                              void* d_out, int out_size)
{
    const float* hidden  = (const float*)d_in[0];
    const void*  ids     = d_in[1];
    const void*  labels  = d_in[2];
    const float* maskp   = (const float*)d_in[3];
    const float* embed_w = (const float*)d_in[4];
    const float* enorm   = (const float*)d_in[5];
    const float* hnorm   = (const float*)d_in[6];
    const float* ehw     = (const float*)d_in[7];
    const float* lnw     = (const float*)d_in[8];
    const float* nw      = (const float*)d_in[9];
    const float* lmw     = (const float*)d_in[10];
    float* logits = (float*)d_out;

    void *pc, *pp, *pn, *pl;
    cudaGetSymbolAddress(&pc, g_combined);
    cudaGetSymbolAddress(&pp, g_proj);
    cudaGetSymbolAddress(&pn, g_normed);
    cudaGetSymbolAddress(&pl, g_nll);

    cudaFuncSetAttribute(gemm_tf32_kernel<true>,
                         cudaFuncAttributeMaxDynamicSharedMemorySize, SMEM_BYTES);
    cudaFuncSetAttribute(gemm_tf32_kernel<false>,
                         cudaFuncAttributeMaxDynamicSharedMemorySize, SMEM_BYTES);

    // 1) gather + enorm/hnorm + concat
    prep_kernel<<<SEQ, 256>>>(hidden, ids, embed_w, enorm, hnorm, (float*)pc);
    // 2) eh_proj: split-tf32 (3-term) for near-fp32 accuracy
    gemm_tf32_kernel<true><<<dim3(HID / BN, SEQ / BM), 256, SMEM_BYTES>>>(
        (const float*)pc, ehw, (float*)pp, SEQ, HID, K2DIM);
    // 3) ln + norm (double rmsnorm)
    norm2_kernel<<<SEQ, 256>>>((const float*)pp, lnw, nw, (float*)pn);
    // 4) lm_head: single tf32 GEMM into d_out
    gemm_tf32_kernel<false><<<dim3(VOC / BN, SEQ / BM), 256, SMEM_BYTES>>>(
        (const float*)pn, lmw, logits, SEQ, VOC, HID);
    // 5) per-row CE
    loss_kernel<<<SEQ - 1, 256>>>(logits, labels, maskp, (float*)pl);
    // 6) masked mean -> last output element
    final_kernel<<<1, 256>>>((const float*)pl, maskp, logits + (size_t)SEQ * VOC);
}

// round 7
// speedup vs baseline: 1.5828x; 1.5828x over previous
#include <cuda.h>
#include <cuda_runtime.h>
#include <cuda_fp16.h>
#include <cstdint>

#define SEQ   1024
#define HID   2048
#define K2DIM 4096
#define VOC   129280
#define EPSV  1e-6f

// single dynamic-smem symbol shared by all kernels
extern __shared__ char dyn_smem[];

// ---------------- scratch (device globals, no allocation) ----------------
__device__ float  g_combined[SEQ * K2DIM];          // 16 MB
__device__ float  g_proj[SEQ * HID];                // 8 MB
__device__ __half g_a16[SEQ * HID];                 // 4 MB (normed, fp16)
__device__ __half g_b16[(size_t)VOC * HID];         // 529 MB (lm_head_w fp16)
__device__ float  g_nll[SEQ];

// ---------------- helpers ----------------
__device__ __forceinline__ unsigned h2_as_u32(__half2 h) {
    union { __half2 h; unsigned u; } c; c.h = h; return c.u;
}
__device__ __forceinline__ bool detect_i64(const int* w) {
    bool z = true;
#pragma unroll
    for (int j = 1; j < 32; j += 2) z = z && (w[j] == 0);
    return z;
}
__device__ __forceinline__ int load_idx(const void* p, int i, bool is64) {
    return is64 ? (int)((const long long*)p)[i] : ((const int*)p)[i];
}
__device__ __forceinline__ float block_sum256(float v, volatile float* red) {
#pragma unroll
    for (int o = 16; o > 0; o >>= 1) v += __shfl_xor_sync(0xffffffffu, v, o);
    if ((threadIdx.x & 31) == 0) red[threadIdx.x >> 5] = v;
    __syncthreads();
    float t = red[0] + red[1] + red[2] + red[3] + red[4] + red[5] + red[6] + red[7];
    __syncthreads();
    return t;
}

__device__ __forceinline__ void cp_async16(void* smem, const void* gmem) {
    unsigned sa = (unsigned)__cvta_generic_to_shared(smem);
    asm volatile("cp.async.ca.shared.global [%0], [%1], 16;" :: "r"(sa), "l"(gmem));
}
__device__ __forceinline__ void cp_commit() { asm volatile("cp.async.commit_group;"); }
__device__ __forceinline__ void cp_wait0() { asm volatile("cp.async.wait_group 0;"); }
__device__ __forceinline__ void cp_wait1() { asm volatile("cp.async.wait_group 1;"); }

// ---------------- kernel A: gather + enorm + hnorm + concat ----------------
__global__ void __launch_bounds__(256) prep_kernel(
    const float* __restrict__ hidden, const void* __restrict__ ids,
    const float* __restrict__ embed_w, const float* __restrict__ enorm_w,
    const float* __restrict__ hnorm_w, float* __restrict__ combined)
{
    __shared__ float s_e[HID];
    __shared__ float s_h[HID];
    __shared__ float red[8];
    __shared__ int s_id;
    int tid = threadIdx.x, sid = blockIdx.x;
    if (tid == 0) {
        bool is64 = detect_i64((const int*)ids);
        s_id = load_idx(ids, sid, is64);
    }
    __syncthreads();
    const float* erow = embed_w + (size_t)s_id * HID;
    const float* hrow = hidden + (size_t)sid * HID;
    float se = 0.f, sh = 0.f;
    for (int j = tid; j < HID; j += 256) {
        float e = erow[j], h = hrow[j];
        s_e[j] = e; s_h[j] = h;
        se += e * e; sh += h * h;
    }
    float vse = block_sum256(se, red);
    float vsh = block_sum256(sh, red);
    float re = rsqrtf(vse / HID + EPSV);
    float rh = rsqrtf(vsh / HID + EPSV);
    float* out = combined + (size_t)sid * K2DIM;
    for (int j = tid; j < HID; j += 256) {
        out[j]       = enorm_w[j] * s_e[j] * re;
        out[HID + j] = hnorm_w[j] * s_h[j] * rh;
    }
}

// ---------------- double RMSNorm (ln then norm) -> fp16 output ----------------
__global__ void __launch_bounds__(256) norm2_kernel(
    const float* __restrict__ x, const float* __restrict__ lnw,
    const float* __restrict__ nw, __half* __restrict__ out)
{
    __shared__ float sx[HID];
    __shared__ float red[8];
    int sid = blockIdx.x, tid = threadIdx.x;
    const float* row = x + (size_t)sid * HID;
    float ss = 0.f;
    for (int j = tid; j < HID; j += 256) { float v = row[j]; sx[j] = v; ss += v * v; }
    float r1 = rsqrtf(block_sum256(ss, red) / HID + EPSV);
    float ss2 = 0.f;
    for (int j = tid; j < HID; j += 256) { float p = lnw[j] * sx[j] * r1; sx[j] = p; ss2 += p * p; }
    float r2 = rsqrtf(block_sum256(ss2, red) / HID + EPSV);
    __half* o = out + (size_t)sid * HID;
    for (int j = tid; j < HID; j += 256) o[j] = __float2half_rn(nw[j] * sx[j] * r2);
}

// ---------------- f32 -> f16 bulk convert (lm_head weights) ----------------
__global__ void __launch_bounds__(256) cvt_kernel(
    const float* __restrict__ in, __half* __restrict__ out)
{
    size_t i = ((size_t)blockIdx.x * 256 + threadIdx.x) * 8;
    float4 v0 = *reinterpret_cast<const float4*>(in + i);
    float4 v1 = *reinterpret_cast<const float4*>(in + i + 4);
    uint4 pk;
    pk.x = h2_as_u32(__floats2half2_rn(v0.x, v0.y));
    pk.y = h2_as_u32(__floats2half2_rn(v0.z, v0.w));
    pk.z = h2_as_u32(__floats2half2_rn(v1.x, v1.y));
    pk.w = h2_as_u32(__floats2half2_rn(v1.z, v1.w));
    *reinterpret_cast<uint4*>(out + i) = pk;
}

// =======================================================================
// eh_proj: split-tf32 mma.sync GEMM (precision-critical, small)
// =======================================================================
#define BM 128
#define BN 128
#define BK 32
#define LDT 36
#define SMEM_BYTES (4 * BM * LDT * 4)

__device__ __forceinline__ unsigned cvt_tf32(float x) {
    unsigned r; asm("cvt.rna.tf32.f32 %0, %1;" : "=r"(r) : "f"(x)); return r;
}
__device__ __forceinline__ void mma_tf32(float c[4], const unsigned a[4], const unsigned b[2]) {
    asm volatile(
        "mma.sync.aligned.m16n8k8.row.col.f32.tf32.tf32.f32 "
        "{%0,%1,%2,%3}, {%4,%5,%6,%7}, {%8,%9}, {%0,%1,%2,%3};"
        : "+f"(c[0]), "+f"(c[1]), "+f"(c[2]), "+f"(c[3])
        : "r"(a[0]), "r"(a[1]), "r"(a[2]), "r"(a[3]), "r"(b[0]), "r"(b[1]));
}

__device__ __forceinline__ void load_tile_f32(
    const float* __restrict__ Ab, const float* __restrict__ Bb,
    float* As, float* Bs, int K, int kt, int st, int tid)
{
    int k0 = kt * BK;
    float* as = As + st * (BM * LDT);
    float* bs = Bs + st * (BM * LDT);
#pragma unroll
    for (int i = 0; i < 4; i++) {
        int idx = tid + i * 256;
        int r = idx >> 3;
        int cg = (idx & 7) * 4;
        cp_async16(as + r * LDT + cg, Ab + (size_t)r * K + k0 + cg);
        cp_async16(bs + r * LDT + cg, Bb + (size_t)r * K + k0 + cg);
    }
}

__global__ void __launch_bounds__(256) gemm_split_kernel(
    const float* __restrict__ A, const float* __restrict__ Bw,
    float* __restrict__ C, int M, int N, int K)
{
    float* smemf = (float*)dyn_smem;
    float* As = smemf;
    float* Bs = smemf + 2 * BM * LDT;

    int tid = threadIdx.x;
    int lane = tid & 31;
    int warp = tid >> 5;
    int wm = warp & 1;
    int wn = warp >> 1;
    int bm = blockIdx.y * BM;
    int bn = blockIdx.x * BN;
    const float* Ab = A + (size_t)bm * K;
    const float* Bb = Bw + (size_t)bn * K;

    float acc[4][4][4];
#pragma unroll
    for (int i = 0; i < 4; i++)
#pragma unroll
        for (int j = 0; j < 4; j++)
#pragma unroll
            for (int q = 0; q < 4; q++) acc[i][j][q] = 0.f;

    int KT = K / BK;
    load_tile_f32(Ab, Bb, As, Bs, K, 0, 0, tid);
    cp_commit();

    int gid = lane >> 2, tig = lane & 3;

    for (int kt = 0; kt < KT; ++kt) {
        int cur = kt & 1;
        cp_wait0();
        __syncthreads();
        if (kt + 1 < KT) { load_tile_f32(Ab, Bb, As, Bs, K, kt + 1, cur ^ 1, tid); cp_commit(); }

        const float* Asc = As + cur * (BM * LDT);
        const float* Bsc = Bs + cur * (BM * LDT);
#pragma unroll
        for (int kk = 0; kk < BK; kk += 8) {
            unsigned af[4][4], bf[4][2];
            unsigned al[4][4], bl[4][2];
#pragma unroll
            for (int mi = 0; mi < 4; mi++) {
                const float* p = Asc + (wm * 64 + mi * 16 + gid) * LDT + kk + tig;
                float x0 = p[0], x1 = p[8 * LDT], x2 = p[4], x3 = p[8 * LDT + 4];
                af[mi][0] = cvt_tf32(x0); af[mi][1] = cvt_tf32(x1);
                af[mi][2] = cvt_tf32(x2); af[mi][3] = cvt_tf32(x3);
                al[mi][0] = cvt_tf32(x0 - __uint_as_float(af[mi][0]));
                al[mi][1] = cvt_tf32(x1 - __uint_as_float(af[mi][1]));
                al[mi][2] = cvt_tf32(x2 - __uint_as_float(af[mi][2]));
                al[mi][3] = cvt_tf32(x3 - __uint_as_float(af[mi][3]));
            }
#pragma unroll
            for (int ni = 0; ni < 4; ni++) {
                const float* p = Bsc + (wn * 32 + ni * 8 + gid) * LDT + kk + tig;
                float y0 = p[0], y1 = p[4];
                bf[ni][0] = cvt_tf32(y0); bf[ni][1] = cvt_tf32(y1);
                bl[ni][0] = cvt_tf32(y0 - __uint_as_float(bf[ni][0]));
                bl[ni][1] = cvt_tf32(y1 - __uint_as_float(bf[ni][1]));
            }
#pragma unroll
            for (int mi = 0; mi < 4; mi++)
#pragma unroll
                for (int ni = 0; ni < 4; ni++) {
                    mma_tf32(acc[mi][ni], af[mi], bf[ni]);
                    mma_tf32(acc[mi][ni], al[mi], bf[ni]);
                    mma_tf32(acc[mi][ni], af[mi], bl[ni]);
                }
        }
    }

    float* Cb = C + (size_t)(bm + wm * 64) * N + bn + wn * 32;
#pragma unroll
    for (int mi = 0; mi < 4; mi++) {
#pragma unroll
        for (int ni = 0; ni < 4; ni++) {
            int r = mi * 16 + gid;
            int c = ni * 8 + tig * 2;
            float2 v0 = make_float2(acc[mi][ni][0], acc[mi][ni][1]);
            float2 v1 = make_float2(acc[mi][ni][2], acc[mi][ni][3]);
            *reinterpret_cast<float2*>(Cb + (size_t)r * N + c) = v0;
            *reinterpret_cast<float2*>(Cb + (size_t)(r + 8) * N + c) = v1;
        }
    }
}

// =======================================================================
// lm_head: fp16 mma.sync m16n8k16 GEMM
//   C[1024, 129280] = A16[1024, 2048] * B16[129280, 2048]^T
//   CTA tile 256x128, 512 threads (16 warps: 4M x 4N, 64x32 per warp)
//   BK=64 fp16, 3-stage cp.async pipeline.
//   grid = (M-tiles=4 [fast], N-tiles=1010) so B is L2/DRAM-shared.
// =======================================================================
#define LM_BM   256
#define LM_BN   128
#define LM_BK   64
#define LM_LDK  72                       // padded row (halves): 144B, conflict-free
#define LM_ASZ  (LM_BM * LM_LDK)         // 18432 halves
#define LM_BSZ  (LM_BN * LM_LDK)         // 9216 halves
#define LM_STG  (LM_ASZ + LM_BSZ)        // 27648 halves = 55296 B
#define LM_SMEM (3 * LM_STG * 2)         // 165888 B
#define LM_KT   (HID / LM_BK)            // 32

__device__ __forceinline__ void mma_f16(float c[4], const uint32_t a[4], const uint32_t b[2]) {
    asm volatile(
        "mma.sync.aligned.m16n8k16.row.col.f32.f16.f16.f32 "
        "{%0,%1,%2,%3}, {%4,%5,%6,%7}, {%8,%9}, {%0,%1,%2,%3};"
        : "+f"(c[0]), "+f"(c[1]), "+f"(c[2]), "+f"(c[3])
        : "r"(a[0]), "r"(a[1]), "r"(a[2]), "r"(a[3]), "r"(b[0]), "r"(b[1]));
}

__device__ __forceinline__ void lm_load_stage(
    const __half* __restrict__ A16, const __half* __restrict__ B16,
    __half* smem, int kt, int s, int bm, int bn, int tid)
{
    __half* as = smem + s * LM_STG;
    __half* bs = as + LM_ASZ;
    const __half* Ag = A16 + (size_t)bm * HID + kt * LM_BK;
    const __half* Bg = B16 + (size_t)bn * HID + kt * LM_BK;
#pragma unroll
    for (int i = 0; i < 4; i++) {                 // A: 2048 16B-chunks / 512 thr
        int c = tid + i * 512;
        int r = c >> 3, kc = (c & 7) * 8;
        cp_async16(as + r * LM_LDK + kc, Ag + (size_t)r * HID + kc);
    }
#pragma unroll
    for (int i = 0; i < 2; i++) {                 // B: 1024 chunks
        int c = tid + i * 512;
        int r = c >> 3, kc = (c & 7) * 8;
        cp_async16(bs + r * LM_LDK + kc, Bg + (size_t)r * HID + kc);
    }
}

__global__ void __launch_bounds__(512, 1) lm_fp16_kernel(
    const __half* __restrict__ A16, const __half* __restrict__ B16,
    float* __restrict__ C)
{
    __half* smem = (__half*)dyn_smem;
    int tid = threadIdx.x;
    int lane = tid & 31, warp = tid >> 5;
    int wm = warp & 3, wn = warp >> 2;
    int gid = lane >> 2, tig = lane & 3;
    int bm = blockIdx.x * LM_BM;
    int bn = blockIdx.y * LM_BN;

    float acc[4][4][4];
#pragma unroll
    for (int i = 0; i < 4; i++)
#pragma unroll
        for (int j = 0; j < 4; j++)
#pragma unroll
            for (int q = 0; q < 4; q++) acc[i][j][q] = 0.f;

    lm_load_stage(A16, B16, smem, 0, 0, bm, bn, tid); cp_commit();
    lm_load_stage(A16, B16, smem, 1, 1, bm, bn, tid); cp_commit();

    for (int kt = 0; kt < LM_KT; ++kt) {
        if (kt >= LM_KT - 2) cp_wait0(); else cp_wait1();
        __syncthreads();
        if (kt + 2 < LM_KT) {
            lm_load_stage(A16, B16, smem, kt + 2, (kt + 2) % 3, bm, bn, tid);
            cp_commit();
        }
        const __half* as = smem + (kt % 3) * LM_STG + (wm * 64) * LM_LDK;
        const __half* bs = smem + (kt % 3) * LM_STG + LM_ASZ + (wn * 32) * LM_LDK;
#pragma unroll
        for (int kk = 0; kk < 4; kk++) {
            int k0 = kk * 16 + 2 * tig;
            uint32_t af[4][4], bf[4][2];
#pragma unroll
            for (int mi = 0; mi < 4; mi++) {
                const __half* p = as + (mi * 16 + gid) * LM_LDK + k0;
                af[mi][0] = *reinterpret_cast<const uint32_t*>(p);
                af[mi][1] = *reinterpret_cast<const uint32_t*>(p + 8 * LM_LDK);
                af[mi][2] = *reinterpret_cast<const uint32_t*>(p + 8);
                af[mi][3] = *reinterpret_cast<const uint32_t*>(p + 8 * LM_LDK + 8);
            }
#pragma unroll
            for (int ni = 0; ni < 4; ni++) {
                const __half* p = bs + (ni * 8 + gid) * LM_LDK + k0;
                bf[ni][0] = *reinterpret_cast<const uint32_t*>(p);
                bf[ni][1] = *reinterpret_cast<const uint32_t*>(p + 8);
            }
#pragma unroll
            for (int mi = 0; mi < 4; mi++)
#pragma unroll
                for (int ni = 0; ni < 4; ni++)
                    mma_f16(acc[mi][ni], af[mi], bf[ni]);
        }
    }

    float* Cb = C + (size_t)(bm + wm * 64) * VOC + bn + wn * 32;
#pragma unroll
    for (int mi = 0; mi < 4; mi++) {
#pragma unroll
        for (int ni = 0; ni < 4; ni++) {
            int r = mi * 16 + gid;
            int c = ni * 8 + tig * 2;
            float2 v0 = make_float2(acc[mi][ni][0], acc[mi][ni][1]);
            float2 v1 = make_float2(acc[mi][ni][2], acc[mi][ni][3]);
            *reinterpret_cast<float2*>(Cb + (size_t)r * VOC + c) = v0;
            *reinterpret_cast<float2*>(Cb + (size_t)(r + 8) * VOC + c) = v1;
        }
    }
}

// ---------------- loss: per-row online logsumexp ----------------
__global__ void __launch_bounds__(256) loss_kernel(
    const float* __restrict__ logits, const void* __restrict__ labels,
    const float* __restrict__ mask, float* __restrict__ nll_out)
{
    int s = blockIdx.x;
    int tid = threadIdx.x;
    __shared__ int s_lab;
    if (tid == 0) {
        bool is64 = detect_i64((const int*)labels);
        s_lab = load_idx(labels, s + 1, is64);
    }
    __syncthreads();
    const float* row = logits + (size_t)s * VOC;

    float m = -1e30f, sum = 0.f;
    for (int j = tid; j < VOC; j += 256) {
        float x = row[j];
        if (x > m) { sum = sum * __expf(m - x) + 1.f; m = x; }
        else       { sum += __expf(x - m); }
    }
#pragma unroll
    for (int o = 16; o > 0; o >>= 1) {
        float om = __shfl_xor_sync(0xffffffffu, m, o);
        float os = __shfl_xor_sync(0xffffffffu, sum, o);
        float nm = fmaxf(m, om);
        sum = sum * __expf(m - nm) + os * __expf(om - nm);
        m = nm;
    }
    __shared__ float sm[8], ssu[8];
    if ((tid & 31) == 0) { sm[tid >> 5] = m; ssu[tid >> 5] = sum; }
    __syncthreads();
    if (tid == 0) {
        float M0 = sm[0], S0 = ssu[0];
#pragma unroll
        for (int i = 1; i < 8; i++) {
            float nm = fmaxf(M0, sm[i]);
            S0 = S0 * __expf(M0 - nm) + ssu[i] * __expf(sm[i] - nm);
            M0 = nm;
        }
        float lse = M0 + logf(S0);
        float nll = lse - row[s_lab];
        nll_out[s] = nll * mask[s + 1];
    }
}

__global__ void __launch_bounds__(256) final_kernel(
    const float* __restrict__ nll, const float* __restrict__ mask,
    float* __restrict__ out)
{
    __shared__ float red[8];
    int tid = threadIdx.x;
    float a = 0.f, b = 0.f;
    for (int j = tid; j < SEQ - 1; j += 256) { a += nll[j]; b += mask[j + 1]; }
    a = block_sum256(a, red);
    b = block_sum256(b, red);
    if (tid == 0) out[0] = a / (b + 1e-8f);
}

// ---------------- launch ----------------
extern "C" void kernel_launch(void* const* d_in, const int* in_sizes, int n_in,
                              void* d_out, int out_size)
{
    const float* hidden  = (const float*)d_in[0];
    const void*  ids     = d_in[1];
    const void*  labels  = d_in[2];
    const float* maskp   = (const float*)d_in[3];
    const float* embed_w = (const float*)d_in[4];
    const float* enorm   = (const float*)d_in[5];
    const float* hnorm   = (const float*)d_in[6];
    const float* ehw     = (const float*)d_in[7];
    const float* lnw     = (const float*)d_in[8];
    const float* nw      = (const float*)d_in[9];
    const float* lmw     = (const float*)d_in[10];
    float* logits = (float*)d_out;

    void *pc, *pp, *pa16, *pb16, *pl;
    cudaGetSymbolAddress(&pc,   g_combined);
    cudaGetSymbolAddress(&pp,   g_proj);
    cudaGetSymbolAddress(&pa16, g_a16);
    cudaGetSymbolAddress(&pb16, g_b16);
    cudaGetSymbolAddress(&pl,   g_nll);

    cudaFuncSetAttribute(gemm_split_kernel,
                         cudaFuncAttributeMaxDynamicSharedMemorySize, SMEM_BYTES);
    cudaFuncSetAttribute(lm_fp16_kernel,
                         cudaFuncAttributeMaxDynamicSharedMemorySize, LM_SMEM);

    // 0) convert lm_head weights f32 -> f16 (independent of everything else)
    cvt_kernel<<<(int)(((size_t)VOC * HID) / (256 * 8)), 256>>>(lmw, (__half*)pb16);
    // 1) gather + enorm/hnorm + concat
    prep_kernel<<<SEQ, 256>>>(hidden, ids, embed_w, enorm, hnorm, (float*)pc);
    // 2) eh_proj: split-tf32 (3-term) mma.sync for near-fp32 accuracy
    gemm_split_kernel<<<dim3(HID / BN, SEQ / BM), 256, SMEM_BYTES>>>(
        (const float*)pc, ehw, (float*)pp, SEQ, HID, K2DIM);
    // 3) ln + norm (double rmsnorm) -> fp16 A
    norm2_kernel<<<SEQ, 256>>>((const float*)pp, lnw, nw, (__half*)pa16);
    // 4) lm_head: fp16 mma.sync, M-fastest grid for B reuse in L2
    lm_fp16_kernel<<<dim3(SEQ / LM_BM, VOC / LM_BN), 512, LM_SMEM>>>(
        (const __half*)pa16, (const __half*)pb16, logits);
    // 5) per-row CE
    loss_kernel<<<SEQ - 1, 256>>>(logits, labels, maskp, (float*)pl);
    // 6) masked mean -> last output element
    final_kernel<<<1, 256>>>((const float*)pl, maskp, logits + (size_t)SEQ * VOC);
}

// round 8
// speedup vs baseline: 1.6268x; 1.0278x over previous
#include <cuda.h>
#include <cuda_runtime.h>
#include <cuda_fp16.h>
#include <cstdint>

#define SEQ   1024
#define HID   2048
#define K2DIM 4096
#define VOC   129280
#define EPSV  1e-6f
#define NT    (VOC / 128)          // 1010 N-tiles

// single dynamic-smem symbol shared by all kernels
extern __shared__ char dyn_smem[];

// ---------------- scratch (device globals, no allocation) ----------------
__device__ float  g_combined[SEQ * K2DIM];          // 16 MB
__device__ float  g_proj[SEQ * HID];                // 8 MB
__device__ __half g_a16[SEQ * HID];                 // 4 MB (normed, fp16)
__device__ __half g_b16[(size_t)VOC * HID];         // 529 MB (lm_head_w fp16)
__device__ float  g_pmax[(size_t)NT * SEQ];         // 4.1 MB per-tile row max
__device__ float  g_psum[(size_t)NT * SEQ];         // 4.1 MB per-tile row sumexp
__device__ float  g_nll[SEQ];

// ---------------- helpers ----------------
__device__ __forceinline__ unsigned h2_as_u32(__half2 h) {
    union { __half2 h; unsigned u; } c; c.h = h; return c.u;
}
__device__ __forceinline__ bool detect_i64(const int* w) {
    bool z = true;
#pragma unroll
    for (int j = 1; j < 32; j += 2) z = z && (w[j] == 0);
    return z;
}
__device__ __forceinline__ int load_idx(const void* p, int i, bool is64) {
    return is64 ? (int)((const long long*)p)[i] : ((const int*)p)[i];
}
__device__ __forceinline__ float block_sum256(float v, volatile float* red) {
#pragma unroll
    for (int o = 16; o > 0; o >>= 1) v += __shfl_xor_sync(0xffffffffu, v, o);
    if ((threadIdx.x & 31) == 0) red[threadIdx.x >> 5] = v;
    __syncthreads();
    float t = red[0] + red[1] + red[2] + red[3] + red[4] + red[5] + red[6] + red[7];
    __syncthreads();
    return t;
}

__device__ __forceinline__ void cp_async16(void* smem, const void* gmem) {
    unsigned sa = (unsigned)__cvta_generic_to_shared(smem);
    asm volatile("cp.async.ca.shared.global [%0], [%1], 16;" :: "r"(sa), "l"(gmem));
}
__device__ __forceinline__ void cp_commit() { asm volatile("cp.async.commit_group;"); }
__device__ __forceinline__ void cp_wait0() { asm volatile("cp.async.wait_group 0;"); }
__device__ __forceinline__ void cp_wait1() { asm volatile("cp.async.wait_group 1;"); }

// ---------------- kernel A: gather + enorm + hnorm + concat ----------------
__global__ void __launch_bounds__(256) prep_kernel(
    const float* __restrict__ hidden, const void* __restrict__ ids,
    const float* __restrict__ embed_w, const float* __restrict__ enorm_w,
    const float* __restrict__ hnorm_w, float* __restrict__ combined)
{
    __shared__ float s_e[HID];
    __shared__ float s_h[HID];
    __shared__ float red[8];
    __shared__ int s_id;
    int tid = threadIdx.x, sid = blockIdx.x;
    if (tid == 0) {
        bool is64 = detect_i64((const int*)ids);
        s_id = load_idx(ids, sid, is64);
    }
    __syncthreads();
    const float* erow = embed_w + (size_t)s_id * HID;
    const float* hrow = hidden + (size_t)sid * HID;
    float se = 0.f, sh = 0.f;
    for (int j = tid; j < HID; j += 256) {
        float e = erow[j], h = hrow[j];
        s_e[j] = e; s_h[j] = h;
        se += e * e; sh += h * h;
    }
    float vse = block_sum256(se, red);
    float vsh = block_sum256(sh, red);
    float re = rsqrtf(vse / HID + EPSV);
    float rh = rsqrtf(vsh / HID + EPSV);
    float* out = combined + (size_t)sid * K2DIM;
    for (int j = tid; j < HID; j += 256) {
        out[j]       = enorm_w[j] * s_e[j] * re;
        out[HID + j] = hnorm_w[j] * s_h[j] * rh;
    }
}

// ---------------- double RMSNorm (ln then norm) -> fp16 output ----------------
__global__ void __launch_bounds__(256) norm2_kernel(
    const float* __restrict__ x, const float* __restrict__ lnw,
    const float* __restrict__ nw, __half* __restrict__ out)
{
    __shared__ float sx[HID];
    __shared__ float red[8];
    int sid = blockIdx.x, tid = threadIdx.x;
    const float* row = x + (size_t)sid * HID;
    float ss = 0.f;
    for (int j = tid; j < HID; j += 256) { float v = row[j]; sx[j] = v; ss += v * v; }
    float r1 = rsqrtf(block_sum256(ss, red) / HID + EPSV);
    float ss2 = 0.f;
    for (int j = tid; j < HID; j += 256) { float p = lnw[j] * sx[j] * r1; sx[j] = p; ss2 += p * p; }
    float r2 = rsqrtf(block_sum256(ss2, red) / HID + EPSV);
    __half* o = out + (size_t)sid * HID;
    for (int j = tid; j < HID; j += 256) o[j] = __float2half_rn(nw[j] * sx[j] * r2);
}

// ---------------- f32 -> f16 bulk convert (lm_head weights) ----------------
__global__ void __launch_bounds__(256) cvt_kernel(
    const float* __restrict__ in, __half* __restrict__ out)
{
    size_t i = ((size_t)blockIdx.x * 256 + threadIdx.x) * 8;
    float4 v0 = *reinterpret_cast<const float4*>(in + i);
    float4 v1 = *reinterpret_cast<const float4*>(in + i + 4);
    uint4 pk;
    pk.x = h2_as_u32(__floats2half2_rn(v0.x, v0.y));
    pk.y = h2_as_u32(__floats2half2_rn(v0.z, v0.w));
    pk.z = h2_as_u32(__floats2half2_rn(v1.x, v1.y));
    pk.w = h2_as_u32(__floats2half2_rn(v1.z, v1.w));
    *reinterpret_cast<uint4*>(out + i) = pk;
}

// =======================================================================
// eh_proj: split-tf32 mma.sync GEMM (precision-critical, small)
// =======================================================================
#define BM 128
#define BN 128
#define BK 32
#define LDT 36
#define SMEM_BYTES (4 * BM * LDT * 4)

__device__ __forceinline__ unsigned cvt_tf32(float x) {
    unsigned r; asm("cvt.rna.tf32.f32 %0, %1;" : "=r"(r) : "f"(x)); return r;
}
__device__ __forceinline__ void mma_tf32(float c[4], const unsigned a[4], const unsigned b[2]) {
    asm volatile(
        "mma.sync.aligned.m16n8k8.row.col.f32.tf32.tf32.f32 "
        "{%0,%1,%2,%3}, {%4,%5,%6,%7}, {%8,%9}, {%0,%1,%2,%3};"
        : "+f"(c[0]), "+f"(c[1]), "+f"(c[2]), "+f"(c[3])
        : "r"(a[0]), "r"(a[1]), "r"(a[2]), "r"(a[3]), "r"(b[0]), "r"(b[1]));
}

__device__ __forceinline__ void load_tile_f32(
    const float* __restrict__ Ab, const float* __restrict__ Bb,
    float* As, float* Bs, int K, int kt, int st, int tid)
{
    int k0 = kt * BK;
    float* as = As + st * (BM * LDT);
    float* bs = Bs + st * (BM * LDT);
#pragma unroll
    for (int i = 0; i < 4; i++) {
        int idx = tid + i * 256;
        int r = idx >> 3;
        int cg = (idx & 7) * 4;
        cp_async16(as + r * LDT + cg, Ab + (size_t)r * K + k0 + cg);
        cp_async16(bs + r * LDT + cg, Bb + (size_t)r * K + k0 + cg);
    }
}

__global__ void __launch_bounds__(256) gemm_split_kernel(
    const float* __restrict__ A, const float* __restrict__ Bw,
    float* __restrict__ C, int M, int N, int K)
{
    float* smemf = (float*)dyn_smem;
    float* As = smemf;
    float* Bs = smemf + 2 * BM * LDT;

    int tid = threadIdx.x;
    int lane = tid & 31;
    int warp = tid >> 5;
    int wm = warp & 1;
    int wn = warp >> 1;
    int bm = blockIdx.y * BM;
    int bn = blockIdx.x * BN;
    const float* Ab = A + (size_t)bm * K;
    const float* Bb = Bw + (size_t)bn * K;

    float acc[4][4][4];
#pragma unroll
    for (int i = 0; i < 4; i++)
#pragma unroll
        for (int j = 0; j < 4; j++)
#pragma unroll
            for (int q = 0; q < 4; q++) acc[i][j][q] = 0.f;

    int KT = K / BK;
    load_tile_f32(Ab, Bb, As, Bs, K, 0, 0, tid);
    cp_commit();

    int gid = lane >> 2, tig = lane & 3;

    for (int kt = 0; kt < KT; ++kt) {
        int cur = kt & 1;
        cp_wait0();
        __syncthreads();
        if (kt + 1 < KT) { load_tile_f32(Ab, Bb, As, Bs, K, kt + 1, cur ^ 1, tid); cp_commit(); }

        const float* Asc = As + cur * (BM * LDT);
        const float* Bsc = Bs + cur * (BM * LDT);
#pragma unroll
        for (int kk = 0; kk < BK; kk += 8) {
            unsigned af[4][4], bf[4][2];
            unsigned al[4][4], bl[4][2];
#pragma unroll
            for (int mi = 0; mi < 4; mi++) {
                const float* p = Asc + (wm * 64 + mi * 16 + gid) * LDT + kk + tig;
                float x0 = p[0], x1 = p[8 * LDT], x2 = p[4], x3 = p[8 * LDT + 4];
                af[mi][0] = cvt_tf32(x0); af[mi][1] = cvt_tf32(x1);
                af[mi][2] = cvt_tf32(x2); af[mi][3] = cvt_tf32(x3);
                al[mi][0] = cvt_tf32(x0 - __uint_as_float(af[mi][0]));
                al[mi][1] = cvt_tf32(x1 - __uint_as_float(af[mi][1]));
                al[mi][2] = cvt_tf32(x2 - __uint_as_float(af[mi][2]));
                al[mi][3] = cvt_tf32(x3 - __uint_as_float(af[mi][3]));
            }
#pragma unroll
            for (int ni = 0; ni < 4; ni++) {
                const float* p = Bsc + (wn * 32 + ni * 8 + gid) * LDT + kk + tig;
                float y0 = p[0], y1 = p[4];
                bf[ni][0] = cvt_tf32(y0); bf[ni][1] = cvt_tf32(y1);
                bl[ni][0] = cvt_tf32(y0 - __uint_as_float(bf[ni][0]));
                bl[ni][1] = cvt_tf32(y1 - __uint_as_float(bf[ni][1]));
            }
#pragma unroll
            for (int mi = 0; mi < 4; mi++)
#pragma unroll
                for (int ni = 0; ni < 4; ni++) {
                    mma_tf32(acc[mi][ni], af[mi], bf[ni]);
                    mma_tf32(acc[mi][ni], al[mi], bf[ni]);
                    mma_tf32(acc[mi][ni], af[mi], bl[ni]);
                }
        }
    }

    float* Cb = C + (size_t)(bm + wm * 64) * N + bn + wn * 32;
#pragma unroll
    for (int mi = 0; mi < 4; mi++) {
#pragma unroll
        for (int ni = 0; ni < 4; ni++) {
            int r = mi * 16 + gid;
            int c = ni * 8 + tig * 2;
            float2 v0 = make_float2(acc[mi][ni][0], acc[mi][ni][1]);
            float2 v1 = make_float2(acc[mi][ni][2], acc[mi][ni][3]);
            *reinterpret_cast<float2*>(Cb + (size_t)r * N + c) = v0;
            *reinterpret_cast<float2*>(Cb + (size_t)(r + 8) * N + c) = v1;
        }
    }
}

// =======================================================================
// lm_head: fp16 mma.sync m16n8k16 GEMM + fused softmax partials
//   C[1024, 129280] = A16[1024, 2048] * B16[129280, 2048]^T
//   CTA tile 128x128, 256 threads (8 warps: 2M x 4N, 64x32 per warp)
//   BK=64, 3-stage cp.async, 2 CTAs/SM (smem 110.6KB each).
//   grid = (M-tiles=8 [fast], N-tiles=1010) so B is L2/DRAM-shared.
// =======================================================================
#define LM_BM   128
#define LM_BN   128
#define LM_BK   64
#define LM_LDK  72                       // padded row (halves), conflict-free
#define LM_ASZ  (LM_BM * LM_LDK)         // 9216 halves
#define LM_BSZ  (LM_BN * LM_LDK)         // 9216 halves
#define LM_STG  (LM_ASZ + LM_BSZ)        // 18432 halves = 36864 B
#define LM_SMEM (3 * LM_STG * 2)         // 110592 B
#define LM_KT   (HID / LM_BK)            // 32

__device__ __forceinline__ void mma_f16(float c[4], const uint32_t a[4], const uint32_t b[2]) {
    asm volatile(
        "mma.sync.aligned.m16n8k16.row.col.f32.f16.f16.f32 "
        "{%0,%1,%2,%3}, {%4,%5,%6,%7}, {%8,%9}, {%0,%1,%2,%3};"
        : "+f"(c[0]), "+f"(c[1]), "+f"(c[2]), "+f"(c[3])
        : "r"(a[0]), "r"(a[1]), "r"(a[2]), "r"(a[3]), "r"(b[0]), "r"(b[1]));
}

__device__ __forceinline__ void lm_load_stage(
    const __half* __restrict__ A16, const __half* __restrict__ B16,
    __half* smem, int kt, int s, int bm, int bn, int tid)
{
    __half* as = smem + s * LM_STG;
    __half* bs = as + LM_ASZ;
    const __half* Ag = A16 + (size_t)bm * HID + kt * LM_BK;
    const __half* Bg = B16 + (size_t)bn * HID + kt * LM_BK;
#pragma unroll
    for (int i = 0; i < 4; i++) {                 // A: 1024 16B-chunks / 256 thr
        int c = tid + i * 256;
        int r = c >> 3, kc = (c & 7) * 8;
        cp_async16(as + r * LM_LDK + kc, Ag + (size_t)r * HID + kc);
    }
#pragma unroll
    for (int i = 0; i < 4; i++) {                 // B: 1024 chunks
        int c = tid + i * 256;
        int r = c >> 3, kc = (c & 7) * 8;
        cp_async16(bs + r * LM_LDK + kc, Bg + (size_t)r * HID + kc);
    }
}

__global__ void __launch_bounds__(256, 2) lm_fp16_kernel(
    const __half* __restrict__ A16, const __half* __restrict__ B16,
    float* __restrict__ C, float* __restrict__ pmax, float* __restrict__ psum)
{
    __half* smem = (__half*)dyn_smem;
    int tid = threadIdx.x;
    int lane = tid & 31, warp = tid >> 5;
    int wm = warp & 1, wn = warp >> 1;
    int gid = lane >> 2, tig = lane & 3;
    int bm = blockIdx.x * LM_BM;
    int bn = blockIdx.y * LM_BN;

    float acc[4][4][4];
#pragma unroll
    for (int i = 0; i < 4; i++)
#pragma unroll
        for (int j = 0; j < 4; j++)
#pragma unroll
            for (int q = 0; q < 4; q++) acc[i][j][q] = 0.f;

    lm_load_stage(A16, B16, smem, 0, 0, bm, bn, tid); cp_commit();
    lm_load_stage(A16, B16, smem, 1, 1, bm, bn, tid); cp_commit();

    for (int kt = 0; kt < LM_KT; ++kt) {
        if (kt >= LM_KT - 2) cp_wait0(); else cp_wait1();
        __syncthreads();
        if (kt + 2 < LM_KT) {
            lm_load_stage(A16, B16, smem, kt + 2, (kt + 2) % 3, bm, bn, tid);
            cp_commit();
        }
        const __half* as = smem + (kt % 3) * LM_STG + (wm * 64) * LM_LDK;
        const __half* bs = smem + (kt % 3) * LM_STG + LM_ASZ + (wn * 32) * LM_LDK;
#pragma unroll
        for (int kk = 0; kk < 4; kk++) {
            int k0 = kk * 16 + 2 * tig;
            uint32_t af[4][4], bf[4][2];
#pragma unroll
            for (int mi = 0; mi < 4; mi++) {
                const __half* p = as + (mi * 16 + gid) * LM_LDK + k0;
                af[mi][0] = *reinterpret_cast<const uint32_t*>(p);
                af[mi][1] = *reinterpret_cast<const uint32_t*>(p + 8 * LM_LDK);
                af[mi][2] = *reinterpret_cast<const uint32_t*>(p + 8);
                af[mi][3] = *reinterpret_cast<const uint32_t*>(p + 8 * LM_LDK + 8);
            }
#pragma unroll
            for (int ni = 0; ni < 4; ni++) {
                const __half* p = bs + (ni * 8 + gid) * LM_LDK + k0;
                bf[ni][0] = *reinterpret_cast<const uint32_t*>(p);
                bf[ni][1] = *reinterpret_cast<const uint32_t*>(p + 8);
            }
#pragma unroll
            for (int mi = 0; mi < 4; mi++)
#pragma unroll
                for (int ni = 0; ni < 4; ni++)
                    mma_f16(acc[mi][ni], af[mi], bf[ni]);
        }
    }

    // ---- store logits ----
    float* Cb = C + (size_t)(bm + wm * 64) * VOC + bn + wn * 32;
#pragma unroll
    for (int mi = 0; mi < 4; mi++) {
#pragma unroll
        for (int ni = 0; ni < 4; ni++) {
            int r = mi * 16 + gid;
            int c = ni * 8 + tig * 2;
            float2 v0 = make_float2(acc[mi][ni][0], acc[mi][ni][1]);
            float2 v1 = make_float2(acc[mi][ni][2], acc[mi][ni][3]);
            *reinterpret_cast<float2*>(Cb + (size_t)r * VOC + c) = v0;
            *reinterpret_cast<float2*>(Cb + (size_t)(r + 8) * VOC + c) = v1;
        }
    }

    // ---- fused per-row softmax partials over this 128-col tile ----
    __syncthreads();                       // stages no longer needed
    float* pm = (float*)dyn_smem;          // 128 rows x 4 wn
    float* ps = pm + 128 * 4;
#pragma unroll
    for (int mi = 0; mi < 4; mi++) {
#pragma unroll
        for (int h = 0; h < 2; h++) {
            float m0 = -1e30f;
#pragma unroll
            for (int ni = 0; ni < 4; ni++)
                m0 = fmaxf(m0, fmaxf(acc[mi][ni][2 * h], acc[mi][ni][2 * h + 1]));
            float s0 = 0.f;
#pragma unroll
            for (int ni = 0; ni < 4; ni++)
                s0 += __expf(acc[mi][ni][2 * h] - m0) + __expf(acc[mi][ni][2 * h + 1] - m0);
#pragma unroll
            for (int o = 1; o <= 2; o <<= 1) {         // quad reduce (tig)
                float om = __shfl_xor_sync(0xffffffffu, m0, o);
                float os = __shfl_xor_sync(0xffffffffu, s0, o);
                float nm = fmaxf(m0, om);
                s0 = s0 * __expf(m0 - nm) + os * __expf(om - nm);
                m0 = nm;
            }
            if (tig == 0) {
                int lr = wm * 64 + mi * 16 + h * 8 + gid;
                pm[lr * 4 + wn] = m0;
                ps[lr * 4 + wn] = s0;
            }
        }
    }
    __syncthreads();
    if (tid < 128) {
        float m0 = pm[tid * 4], s0 = ps[tid * 4];
#pragma unroll
        for (int w = 1; w < 4; w++) {
            float om = pm[tid * 4 + w], os = ps[tid * 4 + w];
            float nm = fmaxf(m0, om);
            s0 = s0 * __expf(m0 - nm) + os * __expf(om - nm);
            m0 = nm;
        }
        size_t idx = (size_t)blockIdx.y * SEQ + bm + tid;
        pmax[idx] = m0;
        psum[idx] = s0;
    }
}

// ---------------- loss: merge per-tile partials ----------------
__global__ void __launch_bounds__(256) loss_reduce_kernel(
    const float* __restrict__ logits, const float* __restrict__ pmax,
    const float* __restrict__ psum, const void* __restrict__ labels,
    const float* __restrict__ mask, float* __restrict__ nll_out)
{
    int s = blockIdx.x;          // row 0..SEQ-2 (uses labels[s+1])
    int tid = threadIdx.x;
    float m = -1e30f, su = 0.f;
    for (int nt = tid; nt < NT; nt += 256) {
        float om = pmax[(size_t)nt * SEQ + s];
        float os = psum[(size_t)nt * SEQ + s];
        float nm = fmaxf(m, om);
        su = su * __expf(m - nm) + os * __expf(om - nm);
        m = nm;
    }
#pragma unroll
    for (int o = 16; o > 0; o >>= 1) {
        float om = __shfl_xor_sync(0xffffffffu, m, o);
        float os = __shfl_xor_sync(0xffffffffu, su, o);
        float nm = fmaxf(m, om);
        su = su * __expf(m - nm) + os * __expf(om - nm);
        m = nm;
    }
    __shared__ float sm[8], ssu[8];
    if ((tid & 31) == 0) { sm[tid >> 5] = m; ssu[tid >> 5] = su; }
    __syncthreads();
    if (tid == 0) {
        float M0 = sm[0], S0 = ssu[0];
#pragma unroll
        for (int i = 1; i < 8; i++) {
            float nm = fmaxf(M0, sm[i]);
            S0 = S0 * __expf(M0 - nm) + ssu[i] * __expf(sm[i] - nm);
            M0 = nm;
        }
        bool is64 = detect_i64((const int*)labels);
        int lab = load_idx(labels, s + 1, is64);
        float lse = M0 + logf(S0);
        float nll = lse - logits[(size_t)s * VOC + lab];
        nll_out[s] = nll * mask[s + 1];
    }
}

__global__ void __launch_bounds__(256) final_kernel(
    const float* __restrict__ nll, const float* __restrict__ mask,
    float* __restrict__ out)
{
    __shared__ float red[8];
    int tid = threadIdx.x;
    float a = 0.f, b = 0.f;
    for (int j = tid; j < SEQ - 1; j += 256) { a += nll[j]; b += mask[j + 1]; }
    a = block_sum256(a, red);
    b = block_sum256(b, red);
    if (tid == 0) out[0] = a / (b + 1e-8f);
}

// ---------------- launch ----------------
extern "C" void kernel_launch(void* const* d_in, const int* in_sizes, int n_in,
                              void* d_out, int out_size)
{
    const float* hidden  = (const float*)d_in[0];
    const void*  ids     = d_in[1];
    const void*  labels  = d_in[2];
    const float* maskp   = (const float*)d_in[3];
    const float* embed_w = (const float*)d_in[4];
    const float* enorm   = (const float*)d_in[5];
    const float* hnorm   = (const float*)d_in[6];
    const float* ehw     = (const float*)d_in[7];
    const float* lnw     = (const float*)d_in[8];
    const float* nw      = (const float*)d_in[9];
    const float* lmw     = (const float*)d_in[10];
    float* logits = (float*)d_out;

    void *pc, *pp, *pa16, *pb16, *ppm, *pps, *pl;
    cudaGetSymbolAddress(&pc,   g_combined);
    cudaGetSymbolAddress(&pp,   g_proj);
    cudaGetSymbolAddress(&pa16, g_a16);
    cudaGetSymbolAddress(&pb16, g_b16);
    cudaGetSymbolAddress(&ppm,  g_pmax);
    cudaGetSymbolAddress(&pps,  g_psum);
    cudaGetSymbolAddress(&pl,   g_nll);

    cudaFuncSetAttribute(gemm_split_kernel,
                         cudaFuncAttributeMaxDynamicSharedMemorySize, SMEM_BYTES);
    cudaFuncSetAttribute(lm_fp16_kernel,
                         cudaFuncAttributeMaxDynamicSharedMemorySize, LM_SMEM);

    // 0) convert lm_head weights f32 -> f16
    cvt_kernel<<<(int)(((size_t)VOC * HID) / (256 * 8)), 256>>>(lmw, (__half*)pb16);
    // 1) gather + enorm/hnorm + concat
    prep_kernel<<<SEQ, 256>>>(hidden, ids, embed_w, enorm, hnorm, (float*)pc);
    // 2) eh_proj: split-tf32 (3-term) mma.sync for near-fp32 accuracy
    gemm_split_kernel<<<dim3(HID / BN, SEQ / BM), 256, SMEM_BYTES>>>(
        (const float*)pc, ehw, (float*)pp, SEQ, HID, K2DIM);
    // 3) ln + norm (double rmsnorm) -> fp16 A
    norm2_kernel<<<SEQ, 256>>>((const float*)pp, lnw, nw, (__half*)pa16);
    // 4) lm_head: fp16 mma.sync, 2 CTAs/SM, fused softmax partials
    lm_fp16_kernel<<<dim3(SEQ / LM_BM, NT), 256, LM_SMEM>>>(
        (const __half*)pa16, (const __half*)pb16, logits, (float*)ppm, (float*)pps);
    // 5) merge partials -> per-row nll
    loss_reduce_kernel<<<SEQ - 1, 256>>>(logits, (const float*)ppm, (const float*)pps,
                                         labels, maskp, (float*)pl);
    // 6) masked mean -> last output element
    final_kernel<<<1, 256>>>((const float*)pl, maskp, logits + (size_t)SEQ * VOC);
}

// round 9
// speedup vs baseline: 1.7421x; 1.0709x over previous
#include <cuda.h>
#include <cuda_runtime.h>
#include <cuda_fp16.h>
#include <cstdint>

#define SEQ   1024
#define HID   2048
#define K2DIM 4096
#define VOC   129280
#define EPSV  1e-6f
#define NT    (VOC / 128)          // 1010 N-tiles

// single dynamic-smem symbol shared by all kernels
extern __shared__ char dyn_smem[];

// ---------------- scratch (device globals, no allocation) ----------------
__device__ float  g_combined[SEQ * K2DIM];          // 16 MB
__device__ float  g_proj[SEQ * HID];                // 8 MB
__device__ __half g_a16[SEQ * HID];                 // 4 MB (normed, fp16)
__device__ __half g_b16[(size_t)VOC * HID];         // 529 MB (lm_head_w fp16)
__device__ float  g_pmax[(size_t)NT * SEQ];         // 4.1 MB per-tile row max
__device__ float  g_psum[(size_t)NT * SEQ];         // 4.1 MB per-tile row sumexp
__device__ float  g_nll[SEQ];

// ---------------- helpers ----------------
__device__ __forceinline__ unsigned h2_as_u32(__half2 h) {
    union { __half2 h; unsigned u; } c; c.h = h; return c.u;
}
__device__ __forceinline__ bool detect_i64(const int* w) {
    bool z = true;
#pragma unroll
    for (int j = 1; j < 32; j += 2) z = z && (w[j] == 0);
    return z;
}
__device__ __forceinline__ int load_idx(const void* p, int i, bool is64) {
    return is64 ? (int)((const long long*)p)[i] : ((const int*)p)[i];
}
__device__ __forceinline__ float block_sum256(float v, volatile float* red) {
#pragma unroll
    for (int o = 16; o > 0; o >>= 1) v += __shfl_xor_sync(0xffffffffu, v, o);
    if ((threadIdx.x & 31) == 0) red[threadIdx.x >> 5] = v;
    __syncthreads();
    float t = red[0] + red[1] + red[2] + red[3] + red[4] + red[5] + red[6] + red[7];
    __syncthreads();
    return t;
}

__device__ __forceinline__ void cp_async16(void* smem, const void* gmem) {
    unsigned sa = (unsigned)__cvta_generic_to_shared(smem);
    asm volatile("cp.async.ca.shared.global [%0], [%1], 16;" :: "r"(sa), "l"(gmem));
}
__device__ __forceinline__ void cp_commit() { asm volatile("cp.async.commit_group;"); }
__device__ __forceinline__ void cp_wait0() { asm volatile("cp.async.wait_group 0;"); }
__device__ __forceinline__ void cp_wait1() { asm volatile("cp.async.wait_group 1;"); }

__device__ __forceinline__ void ldsm_x4(uint32_t& r0, uint32_t& r1, uint32_t& r2,
                                        uint32_t& r3, uint32_t saddr) {
    asm volatile("ldmatrix.sync.aligned.m8n8.x4.shared.b16 {%0,%1,%2,%3}, [%4];"
        : "=r"(r0), "=r"(r1), "=r"(r2), "=r"(r3) : "r"(saddr));
}

// ---------------- kernel A: gather + enorm + hnorm + concat ----------------
__global__ void __launch_bounds__(256) prep_kernel(
    const float* __restrict__ hidden, const void* __restrict__ ids,
    const float* __restrict__ embed_w, const float* __restrict__ enorm_w,
    const float* __restrict__ hnorm_w, float* __restrict__ combined)
{
    __shared__ float s_e[HID];
    __shared__ float s_h[HID];
    __shared__ float red[8];
    __shared__ int s_id;
    int tid = threadIdx.x, sid = blockIdx.x;
    if (tid == 0) {
        bool is64 = detect_i64((const int*)ids);
        s_id = load_idx(ids, sid, is64);
    }
    __syncthreads();
    const float* erow = embed_w + (size_t)s_id * HID;
    const float* hrow = hidden + (size_t)sid * HID;
    float se = 0.f, sh = 0.f;
    for (int j = tid; j < HID; j += 256) {
        float e = erow[j], h = hrow[j];
        s_e[j] = e; s_h[j] = h;
        se += e * e; sh += h * h;
    }
    float vse = block_sum256(se, red);
    float vsh = block_sum256(sh, red);
    float re = rsqrtf(vse / HID + EPSV);
    float rh = rsqrtf(vsh / HID + EPSV);
    float* out = combined + (size_t)sid * K2DIM;
    for (int j = tid; j < HID; j += 256) {
        out[j]       = enorm_w[j] * s_e[j] * re;
        out[HID + j] = hnorm_w[j] * s_h[j] * rh;
    }
}

// ---------------- double RMSNorm (ln then norm) -> fp16 output ----------------
__global__ void __launch_bounds__(256) norm2_kernel(
    const float* __restrict__ x, const float* __restrict__ lnw,
    const float* __restrict__ nw, __half* __restrict__ out)
{
    __shared__ float sx[HID];
    __shared__ float red[8];
    int sid = blockIdx.x, tid = threadIdx.x;
    const float* row = x + (size_t)sid * HID;
    float ss = 0.f;
    for (int j = tid; j < HID; j += 256) { float v = row[j]; sx[j] = v; ss += v * v; }
    float r1 = rsqrtf(block_sum256(ss, red) / HID + EPSV);
    float ss2 = 0.f;
    for (int j = tid; j < HID; j += 256) { float p = lnw[j] * sx[j] * r1; sx[j] = p; ss2 += p * p; }
    float r2 = rsqrtf(block_sum256(ss2, red) / HID + EPSV);
    __half* o = out + (size_t)sid * HID;
    for (int j = tid; j < HID; j += 256) o[j] = __float2half_rn(nw[j] * sx[j] * r2);
}

// ---------------- f32 -> f16 bulk convert (lm_head weights) ----------------
__global__ void __launch_bounds__(256) cvt_kernel(
    const float* __restrict__ in, __half* __restrict__ out)
{
    size_t i = ((size_t)blockIdx.x * 256 + threadIdx.x) * 8;
    float4 v0 = *reinterpret_cast<const float4*>(in + i);
    float4 v1 = *reinterpret_cast<const float4*>(in + i + 4);
    uint4 pk;
    pk.x = h2_as_u32(__floats2half2_rn(v0.x, v0.y));
    pk.y = h2_as_u32(__floats2half2_rn(v0.z, v0.w));
    pk.z = h2_as_u32(__floats2half2_rn(v1.x, v1.y));
    pk.w = h2_as_u32(__floats2half2_rn(v1.z, v1.w));
    *reinterpret_cast<uint4*>(out + i) = pk;
}

// =======================================================================
// eh_proj: split-tf32 mma.sync GEMM (precision-critical, small)
// =======================================================================
#define BM 128
#define BN 128
#define BK 32
#define LDT 36
#define SMEM_BYTES (4 * BM * LDT * 4)

__device__ __forceinline__ unsigned cvt_tf32(float x) {
    unsigned r; asm("cvt.rna.tf32.f32 %0, %1;" : "=r"(r) : "f"(x)); return r;
}
__device__ __forceinline__ void mma_tf32(float c[4], const unsigned a[4], const unsigned b[2]) {
    asm volatile(
        "mma.sync.aligned.m16n8k8.row.col.f32.tf32.tf32.f32 "
        "{%0,%1,%2,%3}, {%4,%5,%6,%7}, {%8,%9}, {%0,%1,%2,%3};"
        : "+f"(c[0]), "+f"(c[1]), "+f"(c[2]), "+f"(c[3])
        : "r"(a[0]), "r"(a[1]), "r"(a[2]), "r"(a[3]), "r"(b[0]), "r"(b[1]));
}

__device__ __forceinline__ void load_tile_f32(
    const float* __restrict__ Ab, const float* __restrict__ Bb,
    float* As, float* Bs, int K, int kt, int st, int tid)
{
    int k0 = kt * BK;
    float* as = As + st * (BM * LDT);
    float* bs = Bs + st * (BM * LDT);
#pragma unroll
    for (int i = 0; i < 4; i++) {
        int idx = tid + i * 256;
        int r = idx >> 3;
        int cg = (idx & 7) * 4;
        cp_async16(as + r * LDT + cg, Ab + (size_t)r * K + k0 + cg);
        cp_async16(bs + r * LDT + cg, Bb + (size_t)r * K + k0 + cg);
    }
}

__global__ void __launch_bounds__(256) gemm_split_kernel(
    const float* __restrict__ A, const float* __restrict__ Bw,
    float* __restrict__ C, int M, int N, int K)
{
    float* smemf = (float*)dyn_smem;
    float* As = smemf;
    float* Bs = smemf + 2 * BM * LDT;

    int tid = threadIdx.x;
    int lane = tid & 31;
    int warp = tid >> 5;
    int wm = warp & 1;
    int wn = warp >> 1;
    int bm = blockIdx.y * BM;
    int bn = blockIdx.x * BN;
    const float* Ab = A + (size_t)bm * K;
    const float* Bb = Bw + (size_t)bn * K;

    float acc[4][4][4];
#pragma unroll
    for (int i = 0; i < 4; i++)
#pragma unroll
        for (int j = 0; j < 4; j++)
#pragma unroll
            for (int q = 0; q < 4; q++) acc[i][j][q] = 0.f;

    int KT = K / BK;
    load_tile_f32(Ab, Bb, As, Bs, K, 0, 0, tid);
    cp_commit();

    int gid = lane >> 2, tig = lane & 3;

    for (int kt = 0; kt < KT; ++kt) {
        int cur = kt & 1;
        cp_wait0();
        __syncthreads();
        if (kt + 1 < KT) { load_tile_f32(Ab, Bb, As, Bs, K, kt + 1, cur ^ 1, tid); cp_commit(); }

        const float* Asc = As + cur * (BM * LDT);
        const float* Bsc = Bs + cur * (BM * LDT);
#pragma unroll
        for (int kk = 0; kk < BK; kk += 8) {
            unsigned af[4][4], bf[4][2];
            unsigned al[4][4], bl[4][2];
#pragma unroll
            for (int mi = 0; mi < 4; mi++) {
                const float* p = Asc + (wm * 64 + mi * 16 + gid) * LDT + kk + tig;
                float x0 = p[0], x1 = p[8 * LDT], x2 = p[4], x3 = p[8 * LDT + 4];
                af[mi][0] = cvt_tf32(x0); af[mi][1] = cvt_tf32(x1);
                af[mi][2] = cvt_tf32(x2); af[mi][3] = cvt_tf32(x3);
                al[mi][0] = cvt_tf32(x0 - __uint_as_float(af[mi][0]));
                al[mi][1] = cvt_tf32(x1 - __uint_as_float(af[mi][1]));
                al[mi][2] = cvt_tf32(x2 - __uint_as_float(af[mi][2]));
                al[mi][3] = cvt_tf32(x3 - __uint_as_float(af[mi][3]));
            }
#pragma unroll
            for (int ni = 0; ni < 4; ni++) {
                const float* p = Bsc + (wn * 32 + ni * 8 + gid) * LDT + kk + tig;
                float y0 = p[0], y1 = p[4];
                bf[ni][0] = cvt_tf32(y0); bf[ni][1] = cvt_tf32(y1);
                bl[ni][0] = cvt_tf32(y0 - __uint_as_float(bf[ni][0]));
                bl[ni][1] = cvt_tf32(y1 - __uint_as_float(bf[ni][1]));
            }
#pragma unroll
            for (int mi = 0; mi < 4; mi++)
#pragma unroll
                for (int ni = 0; ni < 4; ni++) {
                    mma_tf32(acc[mi][ni], af[mi], bf[ni]);
                    mma_tf32(acc[mi][ni], al[mi], bf[ni]);
                    mma_tf32(acc[mi][ni], af[mi], bl[ni]);
                }
        }
    }

    float* Cb = C + (size_t)(bm + wm * 64) * N + bn + wn * 32;
#pragma unroll
    for (int mi = 0; mi < 4; mi++) {
#pragma unroll
        for (int ni = 0; ni < 4; ni++) {
            int r = mi * 16 + gid;
            int c = ni * 8 + tig * 2;
            float2 v0 = make_float2(acc[mi][ni][0], acc[mi][ni][1]);
            float2 v1 = make_float2(acc[mi][ni][2], acc[mi][ni][3]);
            *reinterpret_cast<float2*>(Cb + (size_t)r * N + c) = v0;
            *reinterpret_cast<float2*>(Cb + (size_t)(r + 8) * N + c) = v1;
        }
    }
}

// =======================================================================
// lm_head: fp16 mma.sync m16n8k16 GEMM + fused softmax partials
//   CTA tile 128x128, 256 threads (8 warps: 2M x 4N, 64x32 per warp)
//   BK=64, 3-stage cp.async, 2 CTAs/SM, ldmatrix fragment loads.
//   grid = (M-tiles=8 [fast], N-tiles=1010) so B is L2/DRAM-shared.
// =======================================================================
#define LM_BM   128
#define LM_BN   128
#define LM_BK   64
#define LM_LDK  72                       // padded row (halves), conflict-free
#define LM_ASZ  (LM_BM * LM_LDK)         // 9216 halves
#define LM_BSZ  (LM_BN * LM_LDK)         // 9216 halves
#define LM_STG  (LM_ASZ + LM_BSZ)        // 18432 halves = 36864 B
#define LM_SMEM (3 * LM_STG * 2)         // 110592 B
#define LM_KT   (HID / LM_BK)            // 32

__device__ __forceinline__ void mma_f16(float c[4], const uint32_t a[4], const uint32_t b[2]) {
    asm volatile(
        "mma.sync.aligned.m16n8k16.row.col.f32.f16.f16.f32 "
        "{%0,%1,%2,%3}, {%4,%5,%6,%7}, {%8,%9}, {%0,%1,%2,%3};"
        : "+f"(c[0]), "+f"(c[1]), "+f"(c[2]), "+f"(c[3])
        : "r"(a[0]), "r"(a[1]), "r"(a[2]), "r"(a[3]), "r"(b[0]), "r"(b[1]));
}

__device__ __forceinline__ void lm_load_stage(
    const __half* __restrict__ A16, const __half* __restrict__ B16,
    __half* smem, int kt, int s, int bm, int bn, int tid)
{
    __half* as = smem + s * LM_STG;
    __half* bs = as + LM_ASZ;
    const __half* Ag = A16 + (size_t)bm * HID + kt * LM_BK;
    const __half* Bg = B16 + (size_t)bn * HID + kt * LM_BK;
#pragma unroll
    for (int i = 0; i < 4; i++) {                 // A: 1024 16B-chunks / 256 thr
        int c = tid + i * 256;
        int r = c >> 3, kc = (c & 7) * 8;
        cp_async16(as + r * LM_LDK + kc, Ag + (size_t)r * HID + kc);
    }
#pragma unroll
    for (int i = 0; i < 4; i++) {                 // B: 1024 chunks
        int c = tid + i * 256;
        int r = c >> 3, kc = (c & 7) * 8;
        cp_async16(bs + r * LM_LDK + kc, Bg + (size_t)r * HID + kc);
    }
}

__global__ void __launch_bounds__(256, 2) lm_fp16_kernel(
    const __half* __restrict__ A16, const __half* __restrict__ B16,
    float* __restrict__ C, float* __restrict__ pmax, float* __restrict__ psum)
{
    __half* smem = (__half*)dyn_smem;
    int tid = threadIdx.x;
    int lane = tid & 31, warp = tid >> 5;
    int wm = warp & 1, wn = warp >> 1;
    int gid = lane >> 2, tig = lane & 3;
    int bm = blockIdx.x * LM_BM;
    int bn = blockIdx.y * LM_BN;

    float acc[4][4][4];
#pragma unroll
    for (int i = 0; i < 4; i++)
#pragma unroll
        for (int j = 0; j < 4; j++)
#pragma unroll
            for (int q = 0; q < 4; q++) acc[i][j][q] = 0.f;

    // per-lane ldmatrix half-offsets (within a stage)
    //   A x4 per mi: rows mi*16 + (lane&15), k-half (lane>>4)*8
    //   B x4 per np (covers ni=2np, 2np+1):
    //     rows wn*32 + np*16 + ((lane>>4)<<3) + (lane&7), k-half ((lane>>3)&1)*8
    uint32_t smem_u = (uint32_t)__cvta_generic_to_shared(smem);
    int a_off = (wm * 64 + (lane & 15)) * LM_LDK + ((lane >> 4) << 3);
    int b_off = (wn * 32 + ((lane >> 4) << 3) + (lane & 7)) * LM_LDK + (((lane >> 3) & 1) << 3);

    lm_load_stage(A16, B16, smem, 0, 0, bm, bn, tid); cp_commit();
    lm_load_stage(A16, B16, smem, 1, 1, bm, bn, tid); cp_commit();

    for (int kt = 0; kt < LM_KT; ++kt) {
        if (kt >= LM_KT - 2) cp_wait0(); else cp_wait1();
        __syncthreads();
        if (kt + 2 < LM_KT) {
            lm_load_stage(A16, B16, smem, kt + 2, (kt + 2) % 3, bm, bn, tid);
            cp_commit();
        }
        uint32_t a_base = smem_u + ((kt % 3) * LM_STG + a_off) * 2;
        uint32_t b_base = smem_u + ((kt % 3) * LM_STG + LM_ASZ + b_off) * 2;
#pragma unroll
        for (int kk = 0; kk < 4; kk++) {
            uint32_t af[4][4], bf4[2][4];
#pragma unroll
            for (int mi = 0; mi < 4; mi++)
                ldsm_x4(af[mi][0], af[mi][1], af[mi][2], af[mi][3],
                        a_base + (mi * 16 * LM_LDK + kk * 16) * 2);
#pragma unroll
            for (int np = 0; np < 2; np++)
                ldsm_x4(bf4[np][0], bf4[np][1], bf4[np][2], bf4[np][3],
                        b_base + (np * 16 * LM_LDK + kk * 16) * 2);
#pragma unroll
            for (int mi = 0; mi < 4; mi++) {
#pragma unroll
                for (int np = 0; np < 2; np++) {
                    mma_f16(acc[mi][2 * np],     af[mi], &bf4[np][0]);
                    mma_f16(acc[mi][2 * np + 1], af[mi], &bf4[np][2]);
                }
            }
        }
    }

    // ---- store logits ----
    float* Cb = C + (size_t)(bm + wm * 64) * VOC + bn + wn * 32;
#pragma unroll
    for (int mi = 0; mi < 4; mi++) {
#pragma unroll
        for (int ni = 0; ni < 4; ni++) {
            int r = mi * 16 + gid;
            int c = ni * 8 + tig * 2;
            float2 v0 = make_float2(acc[mi][ni][0], acc[mi][ni][1]);
            float2 v1 = make_float2(acc[mi][ni][2], acc[mi][ni][3]);
            *reinterpret_cast<float2*>(Cb + (size_t)r * VOC + c) = v0;
            *reinterpret_cast<float2*>(Cb + (size_t)(r + 8) * VOC + c) = v1;
        }
    }

    // ---- fused per-row softmax partials over this 128-col tile ----
    __syncthreads();                       // stages no longer needed
    float* pm = (float*)dyn_smem;          // 128 rows x 4 wn
    float* ps = pm + 128 * 4;
#pragma unroll
    for (int mi = 0; mi < 4; mi++) {
#pragma unroll
        for (int h = 0; h < 2; h++) {
            float m0 = -1e30f;
#pragma unroll
            for (int ni = 0; ni < 4; ni++)
                m0 = fmaxf(m0, fmaxf(acc[mi][ni][2 * h], acc[mi][ni][2 * h + 1]));
            float s0 = 0.f;
#pragma unroll
            for (int ni = 0; ni < 4; ni++)
                s0 += __expf(acc[mi][ni][2 * h] - m0) + __expf(acc[mi][ni][2 * h + 1] - m0);
#pragma unroll
            for (int o = 1; o <= 2; o <<= 1) {         // quad reduce (tig)
                float om = __shfl_xor_sync(0xffffffffu, m0, o);
                float os = __shfl_xor_sync(0xffffffffu, s0, o);
                float nm = fmaxf(m0, om);
                s0 = s0 * __expf(m0 - nm) + os * __expf(om - nm);
                m0 = nm;
            }
            if (tig == 0) {
                int lr = wm * 64 + mi * 16 + h * 8 + gid;
                pm[lr * 4 + wn] = m0;
                ps[lr * 4 + wn] = s0;
            }
        }
    }
    __syncthreads();
    if (tid < 128) {
        float m0 = pm[tid * 4], s0 = ps[tid * 4];
#pragma unroll
        for (int w = 1; w < 4; w++) {
            float om = pm[tid * 4 + w], os = ps[tid * 4 + w];
            float nm = fmaxf(m0, om);
            s0 = s0 * __expf(m0 - nm) + os * __expf(om - nm);
            m0 = nm;
        }
        size_t idx = (size_t)blockIdx.y * SEQ + bm + tid;
        pmax[idx] = m0;
        psum[idx] = s0;
    }
}

// ---------------- loss: merge per-tile partials ----------------
__global__ void __launch_bounds__(256) loss_reduce_kernel(
    const float* __restrict__ logits, const float* __restrict__ pmax,
    const float* __restrict__ psum, const void* __restrict__ labels,
    const float* __restrict__ mask, float* __restrict__ nll_out)
{
    int s = blockIdx.x;          // row 0..SEQ-2 (uses labels[s+1])
    int tid = threadIdx.x;
    float m = -1e30f, su = 0.f;
    for (int nt = tid; nt < NT; nt += 256) {
        float om = pmax[(size_t)nt * SEQ + s];
        float os = psum[(size_t)nt * SEQ + s];
        float nm = fmaxf(m, om);
        su = su * __expf(m - nm) + os * __expf(om - nm);
        m = nm;
    }
#pragma unroll
    for (int o = 16; o > 0; o >>= 1) {
        float om = __shfl_xor_sync(0xffffffffu, m, o);
        float os = __shfl_xor_sync(0xffffffffu, su, o);
        float nm = fmaxf(m, om);
        su = su * __expf(m - nm) + os * __expf(om - nm);
        m = nm;
    }
    __shared__ float sm[8], ssu[8];
    if ((tid & 31) == 0) { sm[tid >> 5] = m; ssu[tid >> 5] = su; }
    __syncthreads();
    if (tid == 0) {
        float M0 = sm[0], S0 = ssu[0];
#pragma unroll
        for (int i = 1; i < 8; i++) {
            float nm = fmaxf(M0, sm[i]);
            S0 = S0 * __expf(M0 - nm) + ssu[i] * __expf(sm[i] - nm);
            M0 = nm;
        }
        bool is64 = detect_i64((const int*)labels);
        int lab = load_idx(labels, s + 1, is64);
        float lse = M0 + logf(S0);
        float nll = lse - logits[(size_t)s * VOC + lab];
        nll_out[s] = nll * mask[s + 1];
    }
}

__global__ void __launch_bounds__(256) final_kernel(
    const float* __restrict__ nll, const float* __restrict__ mask,
    float* __restrict__ out)
{
    __shared__ float red[8];
    int tid = threadIdx.x;
    float a = 0.f, b = 0.f;
    for (int j = tid; j < SEQ - 1; j += 256) { a += nll[j]; b += mask[j + 1]; }
    a = block_sum256(a, red);
    b = block_sum256(b, red);
    if (tid == 0) out[0] = a / (b + 1e-8f);
}

// ---------------- launch ----------------
extern "C" void kernel_launch(void* const* d_in, const int* in_sizes, int n_in,
                              void* d_out, int out_size)
{
    const float* hidden  = (const float*)d_in[0];
    const void*  ids     = d_in[1];
    const void*  labels  = d_in[2];
    const float* maskp   = (const float*)d_in[3];
    const float* embed_w = (const float*)d_in[4];
    const float* enorm   = (const float*)d_in[5];
    const float* hnorm   = (const float*)d_in[6];
    const float* ehw     = (const float*)d_in[7];
    const float* lnw     = (const float*)d_in[8];
    const float* nw      = (const float*)d_in[9];
    const float* lmw     = (const float*)d_in[10];
    float* logits = (float*)d_out;

    void *pc, *pp, *pa16, *pb16, *ppm, *pps, *pl;
    cudaGetSymbolAddress(&pc,   g_combined);
    cudaGetSymbolAddress(&pp,   g_proj);
    cudaGetSymbolAddress(&pa16, g_a16);
    cudaGetSymbolAddress(&pb16, g_b16);
    cudaGetSymbolAddress(&ppm,  g_pmax);
    cudaGetSymbolAddress(&pps,  g_psum);
    cudaGetSymbolAddress(&pl,   g_nll);

    cudaFuncSetAttribute(gemm_split_kernel,
                         cudaFuncAttributeMaxDynamicSharedMemorySize, SMEM_BYTES);
    cudaFuncSetAttribute(lm_fp16_kernel,
                         cudaFuncAttributeMaxDynamicSharedMemorySize, LM_SMEM);

    // side stream + events (created lazily on the uncaptured correctness call;
    // reused every call; fork/join makes the capture DAG identical each time)
    static cudaStream_t s2 = nullptr;
    static cudaEvent_t evF = nullptr, evJ = nullptr;
    if (s2 == nullptr) {
        cudaStreamCreateWithFlags(&s2, cudaStreamNonBlocking);
        cudaEventCreateWithFlags(&evF, cudaEventDisableTiming);
        cudaEventCreateWithFlags(&evJ, cudaEventDisableTiming);
    }

    // fork: weight convert runs concurrently with the eh chain
    cudaEventRecord(evF, 0);
    cudaStreamWaitEvent(s2, evF, 0);
    cvt_kernel<<<(int)(((size_t)VOC * HID) / (256 * 8)), 256, 0, s2>>>(lmw, (__half*)pb16);
    cudaEventRecord(evJ, s2);

    // main chain
    prep_kernel<<<SEQ, 256>>>(hidden, ids, embed_w, enorm, hnorm, (float*)pc);
    gemm_split_kernel<<<dim3(HID / BN, SEQ / BM), 256, SMEM_BYTES>>>(
        (const float*)pc, ehw, (float*)pp, SEQ, HID, K2DIM);
    norm2_kernel<<<SEQ, 256>>>((const float*)pp, lnw, nw, (__half*)pa16);

    // join: lm_head needs both g_a16 and g_b16
    cudaStreamWaitEvent(0, evJ, 0);
    lm_fp16_kernel<<<dim3(SEQ / LM_BM, NT), 256, LM_SMEM>>>(
        (const __half*)pa16, (const __half*)pb16, logits, (float*)ppm, (float*)pps);
    loss_reduce_kernel<<<SEQ - 1, 256>>>(logits, (const float*)ppm, (const float*)pps,
                                         labels, maskp, (float*)pl);
    final_kernel<<<1, 256>>>((const float*)pl, maskp, logits + (size_t)SEQ * VOC);
}